// round 2
// baseline (speedup 1.0000x reference)
#include <cuda_runtime.h>
#include <math.h>

// Shapes (hardcoded for this problem instance)
#define BB   2
#define HH   16
#define SS   2048
#define DD   128
#define MM   4096          // memories per head
#define QQ   4096          // B*S queries per head

#define TQ   128           // query tile per CTA
#define TM   128           // memory tile per iteration
#define NTHREADS 256
#define SSTRIDE 132        // sims row stride (33 x 16B, odd -> conflict-free float4)

typedef unsigned long long u64;

// Scratch: normalized queries and keys (32 MB each)
__device__ float g_qn[HH * QQ * DD];
__device__ float g_kn[HH * MM * DD];

// packed fp32x2 FMA: d = a*b + d (lanewise)
#define FMA2(d, a, b) \
    asm("fma.rn.f32x2 %0, %1, %2, %0;" : "+l"(d) : "l"(a), "l"(b))
// duplicate one fp32 into both lanes of a 64-bit pair
#define DUP2(d, x) \
    asm("mov.b64 %0, {%1, %1};" : "=l"(d) : "r"(__float_as_uint(x)))

// ---------------------------------------------------------------------------
// Normalization kernels: one warp per 128-float row
// ---------------------------------------------------------------------------
__global__ void norm_k_kernel(const float* __restrict__ km) {
    int wid  = (blockIdx.x * blockDim.x + threadIdx.x) >> 5;
    int lane = threadIdx.x & 31;
    if (wid >= HH * MM) return;
    float4 v = __ldg(((const float4*)(km + (size_t)wid * DD)) + lane);
    float ss = v.x * v.x + v.y * v.y + v.z * v.z + v.w * v.w;
    #pragma unroll
    for (int o = 16; o > 0; o >>= 1) ss += __shfl_xor_sync(0xffffffffu, ss, o);
    float inv = 1.0f / fmaxf(sqrtf(ss), 1e-11f);
    float4 r = make_float4(v.x * inv, v.y * inv, v.z * inv, v.w * inv);
    ((float4*)(g_kn + (size_t)wid * DD))[lane] = r;
}

__global__ void norm_q_kernel(const float* __restrict__ query) {
    int wid  = (blockIdx.x * blockDim.x + threadIdx.x) >> 5;
    int lane = threadIdx.x & 31;
    if (wid >= HH * QQ) return;
    int h = wid >> 12;          // / 4096
    int q = wid & (QQ - 1);
    int b = q >> 11;            // / 2048
    int s = q & (SS - 1);
    size_t src = ((size_t)((b * HH + h) * SS + s)) * DD;
    float4 v = __ldg(((const float4*)(query + src)) + lane);
    float ss = v.x * v.x + v.y * v.y + v.z * v.z + v.w * v.w;
    #pragma unroll
    for (int o = 16; o > 0; o >>= 1) ss += __shfl_xor_sync(0xffffffffu, ss, o);
    float inv = 1.0f / fmaxf(sqrtf(ss), 1e-11f);
    float4 r = make_float4(v.x * inv, v.y * inv, v.z * inv, v.w * inv);
    ((float4*)(g_qn + (size_t)wid * DD))[lane] = r;
}

// ---------------------------------------------------------------------------
// Tile staging: prefetch (global->regs) and scatter (regs->smem transposed+swizzled)
// element (row, d) -> dst[d*128 + ((row>>2)^((d>>2)&7))*4 + (row&3)]
// ---------------------------------------------------------------------------
__device__ __forceinline__ void prefetch_tile(const float* __restrict__ src,
                                              float4* pf, int tid) {
    #pragma unroll
    for (int i = 0; i < 16; ++i) {
        int f   = i * 256 + tid;        // float4 index 0..4095
        int row = f >> 5;               // 0..127
        int d0  = (f & 31) << 2;        // 0..124
        pf[i] = __ldg((const float4*)(src + (size_t)row * DD + d0));
    }
}

__device__ __forceinline__ void scatter_tile(const float4* pf,
                                             float* __restrict__ dst, int tid) {
    #pragma unroll
    for (int i = 0; i < 16; ++i) {
        int f   = i * 256 + tid;
        int row = f >> 5;
        int d0  = (f & 31) << 2;
        float vv[4] = {pf[i].x, pf[i].y, pf[i].z, pf[i].w};
        int cg = row >> 2;
        int rl = row & 3;
        #pragma unroll
        for (int j = 0; j < 4; ++j) {
            int d = d0 + j;
            dst[d * 128 + (((cg) ^ ((d >> 2) & 7)) << 2) + rl] = vv[j];
        }
    }
}

// Register-resident top-16 insert (static indices after unroll -> no spill)
__device__ __forceinline__ void insert16(float v, int idx,
                                         float tv[16], int ti[16],
                                         float& tmin, int& pmin) {
    #pragma unroll
    for (int j = 0; j < 16; ++j) {
        if (j == pmin) { tv[j] = v; ti[j] = idx; }
    }
    tmin = tv[0]; pmin = 0;
    #pragma unroll
    for (int j = 1; j < 16; ++j) {
        if (tv[j] < tmin) { tmin = tv[j]; pmin = j; }
    }
}

// ---------------------------------------------------------------------------
// Fused kernel: per (head, 128-query tile):
//   loop over M in 128-chunks: f32x2 SGEMM 128x128x128 -> SMEM sims -> top-16
//   then merge halves, gather values, weighted sum, gated blend, write output
// ---------------------------------------------------------------------------
__global__ void __launch_bounds__(NTHREADS, 1)
fused_knn_kernel(const float* __restrict__ vmem,
                 const float* __restrict__ outputs,
                 const float* __restrict__ gate,
                 float* __restrict__ out) {
    extern __shared__ float sm[];
    float* Qs = sm;                 // 16384 floats: Q tile [d][q] swizzled
    float* Ks = sm + 16384;         // 16384 floats: K tile [d][m] swizzled
    float* Ss = sm + 32768;         // 128*SSTRIDE floats: sims [q][m] padded

    const int h     = blockIdx.y;
    const int qbase = blockIdx.x * TQ;
    const int tid   = threadIdx.x;
    const int ty    = tid >> 4;     // 0..15 (query sub-rows)
    const int tx    = tid & 15;     // 0..15 (memory sub-cols)
    const int srow  = tid & 127;    // selection row
    const int shalf = tid >> 7;     // selection half (0/1)

    float4 pf[16];

    // Load and keep the Q tile resident
    prefetch_tile(g_qn + ((size_t)(h * QQ + qbase)) * DD, pf, tid);
    scatter_tile(pf, Qs, tid);

    const float* kh = g_kn + (size_t)h * MM * DD;

    // Prefetch K tile 0
    prefetch_tile(kh, pf, tid);

    // top-16 state (registers)
    float tv[16]; int ti[16];
    #pragma unroll
    for (int j = 0; j < 16; ++j) { tv[j] = -1e30f; ti[j] = 0; }
    float tmin = -1e30f; int pmin = 0;

    for (int mt = 0; mt < MM; mt += TM) {
        __syncthreads();   // prev selection done with Ss; Ks free; Qs ready (1st)
        scatter_tile(pf, Ks, tid);
        __syncthreads();

        // issue next tile's loads early; latency hides behind the GEMM below
        if (mt + TM < MM) prefetch_tile(kh + (size_t)(mt + TM) * DD, pf, tid);

        u64 acc2[8][4];
        #pragma unroll
        for (int i = 0; i < 8; ++i)
            #pragma unroll
            for (int j = 0; j < 4; ++j) acc2[i][j] = 0ULL;

        #pragma unroll 4
        for (int kk = 0; kk < 128; ++kk) {
            int s = (kk >> 2) & 7;
            const float4 a0 = *(const float4*)&Qs[kk * 128 + (((ty * 2)     ^ s) << 2)];
            const float4 a1 = *(const float4*)&Qs[kk * 128 + (((ty * 2 + 1) ^ s) << 2)];
            // B pairs come packed for free from 128-bit loads
            const ulonglong2 b0 = *(const ulonglong2*)&Ks[kk * 128 + (((tx * 2)     ^ s) << 2)];
            const ulonglong2 b1 = *(const ulonglong2*)&Ks[kk * 128 + (((tx * 2 + 1) ^ s) << 2)];
            u64 bp[4] = {b0.x, b0.y, b1.x, b1.y};
            float av[8] = {a0.x, a0.y, a0.z, a0.w, a1.x, a1.y, a1.z, a1.w};
            u64 ad[8];
            #pragma unroll
            for (int i = 0; i < 8; ++i) DUP2(ad[i], av[i]);
            #pragma unroll
            for (int i = 0; i < 8; ++i)
                #pragma unroll
                for (int j = 0; j < 4; ++j) FMA2(acc2[i][j], ad[i], bp[j]);
        }

        // stage sims to shared as packed 8-byte stores
        #pragma unroll
        for (int i = 0; i < 8; ++i) {
            int base = (ty * 8 + i) * SSTRIDE + tx * 8;
            *(u64*)&Ss[base + 0] = acc2[i][0];
            *(u64*)&Ss[base + 2] = acc2[i][1];
            *(u64*)&Ss[base + 4] = acc2[i][2];
            *(u64*)&Ss[base + 6] = acc2[i][3];
        }
        __syncthreads();

        // selection: thread (srow, shalf) scans 64 candidates (float4, no conflicts)
        const float4* sp = (const float4*)(Ss + srow * SSTRIDE + shalf * 64);
        const int base = mt + shalf * 64;
        #pragma unroll 4
        for (int c4 = 0; c4 < 16; ++c4) {
            float4 v = sp[c4];
            int bi = base + c4 * 4;
            if (v.x > tmin) insert16(v.x, bi + 0, tv, ti, tmin, pmin);
            if (v.y > tmin) insert16(v.y, bi + 1, tv, ti, tmin, pmin);
            if (v.z > tmin) insert16(v.z, bi + 2, tv, ti, tmin, pmin);
            if (v.w > tmin) insert16(v.w, bi + 3, tv, ti, tmin, pmin);
        }
    }

    // ---- merge the two halves per row ----
    __syncthreads();
    float* MV = Ks;                       // 128*32 floats
    int*   MI = (int*)(Ks + 4096);        // 128*32 ints
    {
        int mb = srow * 32 + shalf * 16;
        #pragma unroll
        for (int j = 0; j < 16; ++j) { MV[mb + j] = tv[j]; MI[mb + j] = ti[j]; }
    }
    __syncthreads();

    float* FV = Qs;                       // 128*16 floats
    int*   FI = (int*)(Qs + 2048);        // 128*16 ints
    if (tid < 128) {
        #pragma unroll
        for (int j = 0; j < 16; ++j) { tv[j] = -1e30f; ti[j] = 0; }
        tmin = -1e30f; pmin = 0;
        #pragma unroll 2
        for (int c = 0; c < 32; ++c) {
            float v = MV[tid * 32 + c];
            if (v > tmin) insert16(v, MI[tid * 32 + c], tv, ti, tmin, pmin);
        }
        #pragma unroll
        for (int j = 0; j < 16; ++j) { FV[tid * 16 + j] = tv[j]; FI[tid * 16 + j] = ti[j]; }
    }
    __syncthreads();

    // ---- weighted value gather + gated blend ----
    const int row = tid >> 1;             // 0..127
    const int dh  = (tid & 1) << 6;       // 0 or 64
    float accd[64];
    #pragma unroll
    for (int t = 0; t < 64; ++t) accd[t] = 0.0f;

    const float* vh = vmem + (size_t)h * MM * DD;
    for (int j = 0; j < 16; ++j) {
        float sc = FV[row * 16 + j];
        int   ix = FI[row * 16 + j];
        const float4* vp = (const float4*)(vh + (size_t)ix * DD + dh);
        #pragma unroll
        for (int t = 0; t < 16; ++t) {
            float4 w = __ldg(vp + t);
            accd[4 * t + 0] += sc * w.x;
            accd[4 * t + 1] += sc * w.y;
            accd[4 * t + 2] += sc * w.z;
            accd[4 * t + 3] += sc * w.w;
        }
    }

    // Output flat index == wm flat index (raw reshape); gate head from out layout
    size_t l = ((size_t)(h * QQ + qbase + row)) * DD + dh;
    int hout = (int)((l >> 18) & (HH - 1));     // S*D = 2^18
    float gg = 1.0f / (1.0f + expf(-__ldg(gate + hout)));
    float og = 1.0f - gg;

    const float4* op = (const float4*)(outputs + l);
    float4*       wp = (float4*)(out + l);
    #pragma unroll
    for (int t = 0; t < 16; ++t) {
        float4 o = __ldg(op + t);
        float4 r;
        r.x = gg * accd[4 * t + 0] + og * o.x;
        r.y = gg * accd[4 * t + 1] + og * o.y;
        r.z = gg * accd[4 * t + 2] + og * o.z;
        r.w = gg * accd[4 * t + 3] + og * o.w;
        wp[t] = r;
    }
}

// ---------------------------------------------------------------------------
extern "C" void kernel_launch(void* const* d_in, const int* in_sizes, int n_in,
                              void* d_out, int out_size) {
    // metadata order: inputs, query, key, value, outputs, gate, key_memories, value_memories
    const float* query   = (const float*)d_in[1];
    const float* outputs = (const float*)d_in[4];
    const float* gate    = (const float*)d_in[5];
    const float* kmem    = (const float*)d_in[6];
    const float* vmem    = (const float*)d_in[7];
    float* out = (float*)d_out;

    const int smem_bytes = (32768 + 128 * SSTRIDE) * (int)sizeof(float);  // 198656
    cudaFuncSetAttribute(fused_knn_kernel,
                         cudaFuncAttributeMaxDynamicSharedMemorySize, smem_bytes);

    norm_k_kernel<<<(HH * MM) / 8, 256>>>(kmem);
    norm_q_kernel<<<(HH * QQ) / 8, 256>>>(query);

    dim3 grid(QQ / TQ, HH);  // (32, 16)
    fused_knn_kernel<<<grid, NTHREADS, smem_bytes>>>(vmem, outputs, gate, out);
}

// round 4
// speedup vs baseline: 1.0355x; 1.0355x over previous
#include <cuda_runtime.h>
#include <math.h>

// Shapes (hardcoded for this problem instance)
#define BB   2
#define HH   16
#define SS   2048
#define DD   128
#define MM   4096          // memories per head
#define QQ   4096          // B*S queries per head

#define TQ   128           // query tile per CTA
#define TM   128           // memory tile per iteration
#define NTHREADS 256
#define SSTRIDE 132        // sims row stride: divisible by 4 (float4-aligned rows)

typedef unsigned long long u64;

// Scratch: normalized queries and keys (32 MB each)
__device__ float g_qn[HH * QQ * DD];
__device__ float g_kn[HH * MM * DD];

// packed fp32x2 FMA: d = a*b + d (lanewise)
#define FMA2(d, a, b) \
    asm("fma.rn.f32x2 %0, %1, %2, %0;" : "+l"(d) : "l"(a), "l"(b))
// duplicate one fp32 into both lanes of a 64-bit pair
#define DUP2(d, x) \
    asm("mov.b64 %0, {%1, %1};" : "=l"(d) : "r"(__float_as_uint(x)))

// ---------------------------------------------------------------------------
// Normalization kernels: one warp per 128-float row
// ---------------------------------------------------------------------------
__global__ void norm_k_kernel(const float* __restrict__ km) {
    int wid  = (blockIdx.x * blockDim.x + threadIdx.x) >> 5;
    int lane = threadIdx.x & 31;
    if (wid >= HH * MM) return;
    float4 v = __ldg(((const float4*)(km + (size_t)wid * DD)) + lane);
    float ss = v.x * v.x + v.y * v.y + v.z * v.z + v.w * v.w;
    #pragma unroll
    for (int o = 16; o > 0; o >>= 1) ss += __shfl_xor_sync(0xffffffffu, ss, o);
    float inv = 1.0f / fmaxf(sqrtf(ss), 1e-11f);
    float4 r = make_float4(v.x * inv, v.y * inv, v.z * inv, v.w * inv);
    ((float4*)(g_kn + (size_t)wid * DD))[lane] = r;
}

__global__ void norm_q_kernel(const float* __restrict__ query) {
    int wid  = (blockIdx.x * blockDim.x + threadIdx.x) >> 5;
    int lane = threadIdx.x & 31;
    if (wid >= HH * QQ) return;
    int h = wid >> 12;          // / 4096
    int q = wid & (QQ - 1);
    int b = q >> 11;            // / 2048
    int s = q & (SS - 1);
    size_t src = ((size_t)((b * HH + h) * SS + s)) * DD;
    float4 v = __ldg(((const float4*)(query + src)) + lane);
    float ss = v.x * v.x + v.y * v.y + v.z * v.z + v.w * v.w;
    #pragma unroll
    for (int o = 16; o > 0; o >>= 1) ss += __shfl_xor_sync(0xffffffffu, ss, o);
    float inv = 1.0f / fmaxf(sqrtf(ss), 1e-11f);
    float4 r = make_float4(v.x * inv, v.y * inv, v.z * inv, v.w * inv);
    ((float4*)(g_qn + (size_t)wid * DD))[lane] = r;
}

// ---------------------------------------------------------------------------
// Load a 128x128 fp32 tile (row-major [row][d]) into SMEM transposed [d][row]
// with XOR group-swizzle: element (row, d) -> dst[d*128 + ((row>>2)^((d>>2)&7))*4 + (row&3)]
// (direct LDG->STS, no register residency across the GEMM)
// ---------------------------------------------------------------------------
__device__ __forceinline__ void load_tile_T(const float* __restrict__ src,
                                            float* __restrict__ dst, int tid) {
    #pragma unroll
    for (int i = 0; i < 16; ++i) {
        int f   = i * 256 + tid;        // float4 index 0..4095
        int row = f >> 5;               // 0..127
        int d0  = (f & 31) << 2;        // 0..124
        float4 v = __ldg((const float4*)(src + (size_t)row * DD + d0));
        float vv[4] = {v.x, v.y, v.z, v.w};
        int cg = row >> 2;
        int rl = row & 3;
        #pragma unroll
        for (int j = 0; j < 4; ++j) {
            int d = d0 + j;
            dst[d * 128 + (((cg) ^ ((d >> 2) & 7)) << 2) + rl] = vv[j];
        }
    }
}

// Register-resident top-16 insert (static indices after unroll -> no spill)
__device__ __forceinline__ void insert16(float v, int idx,
                                         float tv[16], int ti[16],
                                         float& tmin, int& pmin) {
    #pragma unroll
    for (int j = 0; j < 16; ++j) {
        if (j == pmin) { tv[j] = v; ti[j] = idx; }
    }
    tmin = tv[0]; pmin = 0;
    #pragma unroll
    for (int j = 1; j < 16; ++j) {
        if (tv[j] < tmin) { tmin = tv[j]; pmin = j; }
    }
}

// ---------------------------------------------------------------------------
// Fused kernel: per (head, 128-query tile):
//   loop over M in 128-chunks: f32x2 SGEMM 128x128x128 -> SMEM sims -> top-16
//   then merge halves, gather values, weighted sum, gated blend, write output
//
// Column ownership (per thread): pairs {tx*2 + 32*j, tx*2 + 32*j + 1}, j=0..3
//  -> B operand pairs are conflict-free LDS.64 from the swizzled K tile
//  -> sims staging is STS.64 with <=2-way conflicts
// ---------------------------------------------------------------------------
__global__ void __launch_bounds__(NTHREADS, 1)
fused_knn_kernel(const float* __restrict__ vmem,
                 const float* __restrict__ outputs,
                 const float* __restrict__ gate,
                 float* __restrict__ out) {
    extern __shared__ float sm[];
    float* Qs = sm;                 // 16384 floats: Q tile [d][q] swizzled
    float* Ks = sm + 16384;         // 16384 floats: K tile [d][m] swizzled
    float* Ss = sm + 32768;         // 128*SSTRIDE floats: sims [q][m]

    const int h     = blockIdx.y;
    const int qbase = blockIdx.x * TQ;
    const int tid   = threadIdx.x;
    const int ty    = tid >> 4;     // 0..15 (query sub-rows: rows ty*8..ty*8+7)
    const int tx    = tid & 15;     // 0..15 (column-pair id)
    const int txg   = tx >> 1;      // 0..7  (column 4-group base)
    const int txo   = (tx & 1) << 1;// 0 or 2 (offset within 4-group)
    const int srow  = tid & 127;    // selection row
    const int shalf = tid >> 7;     // selection half (0/1)

    // Load and keep the Q tile resident
    load_tile_T(g_qn + ((size_t)(h * QQ + qbase)) * DD, Qs, tid);

    // top-16 state (registers)
    float tv[16]; int ti[16];
    #pragma unroll
    for (int j = 0; j < 16; ++j) { tv[j] = -1e30f; ti[j] = 0; }
    float tmin = -1e30f; int pmin = 0;

    const float* kh = g_kn + (size_t)h * MM * DD;

    for (int mt = 0; mt < MM; mt += TM) {
        __syncthreads();  // prev selection done with Ss; prev GEMM done with Ks
        load_tile_T(kh + (size_t)mt * DD, Ks, tid);
        __syncthreads();

        u64 acc2[8][4];
        #pragma unroll
        for (int i = 0; i < 8; ++i)
            #pragma unroll
            for (int j = 0; j < 4; ++j) acc2[i][j] = 0ULL;

        #pragma unroll 4
        for (int kk = 0; kk < 128; ++kk) {
            int s = (kk >> 2) & 7;
            const float* qrow = Qs + kk * 128;
            const float* krow = Ks + kk * 128;
            // A: 8 query rows (two swizzled float4 groups)
            const float4 a0 = *(const float4*)&qrow[(((ty * 2)     ^ s) << 2)];
            const float4 a1 = *(const float4*)&qrow[(((ty * 2 + 1) ^ s) << 2)];
            // B: 4 column-pairs at m = tx*2 + 32j (conflict-free LDS.64)
            u64 bp[4];
            #pragma unroll
            for (int j = 0; j < 4; ++j)
                bp[j] = *(const u64*)&krow[(((txg ^ s) + 8 * j) << 2) + txo];
            float av[8] = {a0.x, a0.y, a0.z, a0.w, a1.x, a1.y, a1.z, a1.w};
            u64 ad[8];
            #pragma unroll
            for (int i = 0; i < 8; ++i) DUP2(ad[i], av[i]);
            #pragma unroll
            for (int i = 0; i < 8; ++i)
                #pragma unroll
                for (int j = 0; j < 4; ++j) FMA2(acc2[i][j], ad[i], bp[j]);
        }

        // stage sims: row = ty*8+i, col-pair at tx*2 + 32j (STS.64, ~2-way)
        #pragma unroll
        for (int i = 0; i < 8; ++i) {
            float* srowp = Ss + (ty * 8 + i) * SSTRIDE + tx * 2;
            #pragma unroll
            for (int j = 0; j < 4; ++j)
                *(u64*)&srowp[32 * j] = acc2[i][j];
        }
        __syncthreads();

        // selection: thread (srow, shalf) scans 64 candidates (float4, aligned:
        // srow*132 + shalf*64 is a multiple of 4 floats)
        const float4* sp = (const float4*)(Ss + srow * SSTRIDE + shalf * 64);
        const int base = mt + shalf * 64;
        #pragma unroll 4
        for (int c4 = 0; c4 < 16; ++c4) {
            float4 v = sp[c4];
            int bi = base + c4 * 4;
            if (v.x > tmin) insert16(v.x, bi + 0, tv, ti, tmin, pmin);
            if (v.y > tmin) insert16(v.y, bi + 1, tv, ti, tmin, pmin);
            if (v.z > tmin) insert16(v.z, bi + 2, tv, ti, tmin, pmin);
            if (v.w > tmin) insert16(v.w, bi + 3, tv, ti, tmin, pmin);
        }
    }

    // ---- merge the two halves per row ----
    __syncthreads();
    float* MV = Ks;                       // 128*32 floats
    int*   MI = (int*)(Ks + 4096);        // 128*32 ints
    {
        int mb = srow * 32 + shalf * 16;
        #pragma unroll
        for (int j = 0; j < 16; ++j) { MV[mb + j] = tv[j]; MI[mb + j] = ti[j]; }
    }
    __syncthreads();

    float* FV = Qs;                       // 128*16 floats
    int*   FI = (int*)(Qs + 2048);        // 128*16 ints
    if (tid < 128) {
        #pragma unroll
        for (int j = 0; j < 16; ++j) { tv[j] = -1e30f; ti[j] = 0; }
        tmin = -1e30f; pmin = 0;
        #pragma unroll 2
        for (int c = 0; c < 32; ++c) {
            float v = MV[tid * 32 + c];
            if (v > tmin) insert16(v, MI[tid * 32 + c], tv, ti, tmin, pmin);
        }
        #pragma unroll
        for (int j = 0; j < 16; ++j) { FV[tid * 16 + j] = tv[j]; FI[tid * 16 + j] = ti[j]; }
    }
    __syncthreads();

    // ---- weighted value gather + gated blend ----
    const int row = tid >> 1;             // 0..127
    const int dh  = (tid & 1) << 6;       // 0 or 64
    float accd[64];
    #pragma unroll
    for (int t = 0; t < 64; ++t) accd[t] = 0.0f;

    const float* vh = vmem + (size_t)h * MM * DD;
    for (int j = 0; j < 16; ++j) {
        float sc = FV[row * 16 + j];
        int   ix = FI[row * 16 + j];
        const float4* vp = (const float4*)(vh + (size_t)ix * DD + dh);
        #pragma unroll
        for (int t = 0; t < 16; ++t) {
            float4 w = __ldg(vp + t);
            accd[4 * t + 0] += sc * w.x;
            accd[4 * t + 1] += sc * w.y;
            accd[4 * t + 2] += sc * w.z;
            accd[4 * t + 3] += sc * w.w;
        }
    }

    // Output flat index == wm flat index (raw reshape); gate head from out layout
    size_t l = ((size_t)(h * QQ + qbase + row)) * DD + dh;
    int hout = (int)((l >> 18) & (HH - 1));     // S*D = 2^18
    float gg = 1.0f / (1.0f + expf(-__ldg(gate + hout)));
    float og = 1.0f - gg;

    const float4* op = (const float4*)(outputs + l);
    float4*       wp = (float4*)(out + l);
    #pragma unroll
    for (int t = 0; t < 16; ++t) {
        float4 o = __ldg(op + t);
        float4 r;
        r.x = gg * accd[4 * t + 0] + og * o.x;
        r.y = gg * accd[4 * t + 1] + og * o.y;
        r.z = gg * accd[4 * t + 2] + og * o.z;
        r.w = gg * accd[4 * t + 3] + og * o.w;
        wp[t] = r;
    }
}

// ---------------------------------------------------------------------------
extern "C" void kernel_launch(void* const* d_in, const int* in_sizes, int n_in,
                              void* d_out, int out_size) {
    // metadata order: inputs, query, key, value, outputs, gate, key_memories, value_memories
    const float* query   = (const float*)d_in[1];
    const float* outputs = (const float*)d_in[4];
    const float* gate    = (const float*)d_in[5];
    const float* kmem    = (const float*)d_in[6];
    const float* vmem    = (const float*)d_in[7];
    float* out = (float*)d_out;

    const int smem_bytes = (32768 + 128 * SSTRIDE) * (int)sizeof(float);  // 198656
    cudaFuncSetAttribute(fused_knn_kernel,
                         cudaFuncAttributeMaxDynamicSharedMemorySize, smem_bytes);

    norm_k_kernel<<<(HH * MM) / 8, 256>>>(kmem);
    norm_q_kernel<<<(HH * QQ) / 8, 256>>>(query);

    dim3 grid(QQ / TQ, HH);  // (32, 16)
    fused_knn_kernel<<<grid, NTHREADS, smem_bytes>>>(vmem, outputs, gate, out);
}